// round 2
// baseline (speedup 1.0000x reference)
#include <cuda_runtime.h>

#define EPSBN 1e-5f

// ---------------- device scratch ----------------
__device__ float  g_F1a[3145728];
__device__ float4 g_F1b[3145728];
__device__ float  g_h1[31490048];          // [1024,32,961]
__device__ float  g_part1[32*64*2];
__device__ float  g_bn1p[64];
__device__ float  g_F2a[7372800];          // [1024,32,15,15]
__device__ float4 g_F2b[7372800];
__device__ float  g_h2[12845056];          // [1024,64,196]
__device__ float  g_part2[64*32*2];
__device__ float  g_bn2p[128];
__device__ float  g_p2[3211264];           // [1024,3136]
__device__ float  g_fc1p[8*65536];
__device__ float  g_a1[65536];
__device__ float  g_bn3p[128];

// silu + 4 cubic B-spline bases on knots {-7,-5,...,7}
__device__ __forceinline__ void feats5(float v, float f[5]) {
    f[0] = v / (1.f + expf(-v));
    float b[7];
#pragma unroll
    for (int j = 0; j < 7; j++) {
        float gj = 2.f * j - 7.f;
        b[j] = (v >= gj && v < gj + 2.f) ? 1.f : 0.f;
    }
#pragma unroll
    for (int p = 1; p <= 3; p++) {
        float inv = 1.f / (2.f * p);
#pragma unroll
        for (int j = 0; j < 7 - p; j++) {
            float gj = 2.f * j - 7.f;
            b[j] = ((v - gj) * b[j] + (gj + 2.f * (p + 1) - v) * b[j + 1]) * inv;
        }
    }
    f[1] = b[0]; f[2] = b[1]; f[3] = b[2]; f[4] = b[3];
}

__global__ void feat1_kernel(const float* __restrict__ x) {
    int i = blockIdx.x * 256 + threadIdx.x;
    if (i >= 3145728) return;
    float f[5]; feats5(x[i], f);
    g_F1a[i] = f[0];
    g_F1b[i] = make_float4(f[1], f[2], f[3], f[4]);
}

// conv1 GEMM: M=984064, N=32, K=60 (2 chunks of 30)
__global__ __launch_bounds__(256) void conv1_gemm(const float* __restrict__ wb,
                                                  const float* __restrict__ ws) {
    __shared__ float As[30][256];
    __shared__ float Bs[30][32];
    const int tid = threadIdx.x;
    const int m0 = blockIdx.x * 256;
    const int px = tid & 63, oy = tid >> 6;
    float acc[4][8];
#pragma unroll
    for (int a = 0; a < 4; a++)
#pragma unroll
        for (int o = 0; o < 8; o++) acc[a][o] = 0.f;

    for (int chunk = 0; chunk < 2; chunk++) {
        int i0 = chunk * 6;
        __syncthreads();
        for (int q = tid; q < 960; q += 256) {
            int o = q & 31, kk = q >> 5;
            int ii = kk / 5, t = kk - ii * 5, i = i0 + ii;
            Bs[kk][o] = (t == 0) ? wb[o * 12 + i] : ws[(o * 12 + i) * 4 + (t - 1)];
        }
        for (int q = tid; q < 1536; q += 256) {
            int pos = q & 255, ii = q >> 8;
            int i = i0 + ii;
            int m = m0 + pos;
            int bb = m / 961, r = m - bb * 961;
            int y = r / 31, xx = r - y * 31;
            int c = i >> 2, j = i & 3;
            int pix = ((bb * 3 + c) * 32 + y + (j >> 1)) * 32 + xx + (j & 1);
            float f0 = g_F1a[pix];
            float4 f4 = g_F1b[pix];
            As[ii * 5 + 0][pos] = f0;
            As[ii * 5 + 1][pos] = f4.x;
            As[ii * 5 + 2][pos] = f4.y;
            As[ii * 5 + 3][pos] = f4.z;
            As[ii * 5 + 4][pos] = f4.w;
        }
        __syncthreads();
#pragma unroll 5
        for (int k = 0; k < 30; k++) {
            float4 av = *(const float4*)&As[k][px * 4];
            float4 b0 = *(const float4*)&Bs[k][oy * 8];
            float4 b1 = *(const float4*)&Bs[k][oy * 8 + 4];
            float aa[4] = {av.x, av.y, av.z, av.w};
            float bb[8] = {b0.x, b0.y, b0.z, b0.w, b1.x, b1.y, b1.z, b1.w};
#pragma unroll
            for (int a = 0; a < 4; a++)
#pragma unroll
                for (int o = 0; o < 8; o++) acc[a][o] = fmaf(aa[a], bb[o], acc[a][o]);
        }
    }
#pragma unroll
    for (int a = 0; a < 4; a++) {
        int m = m0 + px * 4 + a;
        int bb = m / 961, r = m - bb * 961;
#pragma unroll
        for (int o = 0; o < 8; o++)
            g_h1[(bb * 32 + oy * 8 + o) * 961 + r] = acc[a][o];
    }
}

__global__ void reduce1_kernel() {
    __shared__ float rs[256], rq[256];
    int c = blockIdx.y, b0 = blockIdx.x * 16;
    float s = 0.f, ss = 0.f;
    for (int b = b0; b < b0 + 16; b++) {
        const float* p = g_h1 + (b * 32 + c) * 961;
        for (int i = threadIdx.x; i < 961; i += 256) { float v = p[i]; s += v; ss += v * v; }
    }
    rs[threadIdx.x] = s; rq[threadIdx.x] = ss; __syncthreads();
    for (int st = 128; st; st >>= 1) {
        if (threadIdx.x < st) { rs[threadIdx.x] += rs[threadIdx.x + st]; rq[threadIdx.x] += rq[threadIdx.x + st]; }
        __syncthreads();
    }
    if (threadIdx.x == 0) {
        g_part1[(c * 64 + blockIdx.x) * 2 + 0] = rs[0];
        g_part1[(c * 64 + blockIdx.x) * 2 + 1] = rq[0];
    }
}

__global__ void reduce2_kernel() {
    __shared__ float rs[256], rq[256];
    int c = blockIdx.y, b0 = blockIdx.x * 32;
    float s = 0.f, ss = 0.f;
    for (int b = b0; b < b0 + 32; b++) {
        const float* p = g_h2 + (b * 64 + c) * 196;
        for (int i = threadIdx.x; i < 196; i += 256) { float v = p[i]; s += v; ss += v * v; }
    }
    rs[threadIdx.x] = s; rq[threadIdx.x] = ss; __syncthreads();
    for (int st = 128; st; st >>= 1) {
        if (threadIdx.x < st) { rs[threadIdx.x] += rs[threadIdx.x + st]; rq[threadIdx.x] += rq[threadIdx.x + st]; }
        __syncthreads();
    }
    if (threadIdx.x == 0) {
        g_part2[(c * 32 + blockIdx.x) * 2 + 0] = rs[0];
        g_part2[(c * 32 + blockIdx.x) * 2 + 1] = rq[0];
    }
}

__global__ void finalize_bn(int which, const float* __restrict__ gam, const float* __restrict__ bet) {
    int c = blockIdx.x;
    const float* part; float* out2; int nparts; float invc;
    if (which == 0) { part = g_part1; out2 = g_bn1p; nparts = 64; invc = 1.f / 984064.f; }
    else            { part = g_part2; out2 = g_bn2p; nparts = 32; invc = 1.f / 200704.f; }
    float s = 0.f, ss = 0.f;
    for (int i = threadIdx.x; i < nparts; i += 32) {
        s  += part[(c * nparts + i) * 2 + 0];
        ss += part[(c * nparts + i) * 2 + 1];
    }
#pragma unroll
    for (int off = 16; off; off >>= 1) {
        s  += __shfl_down_sync(0xffffffffu, s, off);
        ss += __shfl_down_sync(0xffffffffu, ss, off);
    }
    if (threadIdx.x == 0) {
        float mean = s * invc;
        float var  = ss * invc - mean * mean;
        float sc   = gam[c] * rsqrtf(var + EPSBN);
        out2[2 * c + 0] = sc;
        out2[2 * c + 1] = bet[c] - mean * sc;
    }
}

// bn1 + relu + maxpool + conv2 feature generation
__global__ void pool1feat_kernel() {
    int idx = blockIdx.x * 256 + threadIdx.x;
    if (idx >= 7372800) return;
    int xo = idx % 15; int t1 = idx / 15;
    int yo = t1 % 15;  int t2 = t1 / 15;
    int c  = t2 & 31;  int b  = t2 >> 5;
    float sc = g_bn1p[2 * c], sh = g_bn1p[2 * c + 1];
    const float* p = g_h1 + (b * 32 + c) * 961 + (2 * yo) * 31 + 2 * xo;
    float m = fmaf(p[0], sc, sh);
    m = fmaxf(m, fmaf(p[1], sc, sh));
    m = fmaxf(m, fmaf(p[31], sc, sh));
    m = fmaxf(m, fmaf(p[32], sc, sh));
    float v = fmaxf(m, 0.f);
    float f[5]; feats5(v, f);
    g_F2a[idx] = f[0];
    g_F2b[idx] = make_float4(f[1], f[2], f[3], f[4]);
}

// conv2 GEMM: M=200704, N=64, K=640 (16 chunks of 40)
__global__ __launch_bounds__(256) void conv2_gemm(const float* __restrict__ wb,
                                                  const float* __restrict__ ws) {
    __shared__ float As[40][128];
    __shared__ float Bs[40][64];
    const int tid = threadIdx.x;
    const int m0 = blockIdx.x * 128;
    const int px = tid & 31, oy = tid >> 5;
    float acc[4][8];
#pragma unroll
    for (int a = 0; a < 4; a++)
#pragma unroll
        for (int o = 0; o < 8; o++) acc[a][o] = 0.f;

    for (int chunk = 0; chunk < 16; chunk++) {
        int i0 = chunk * 8;
        __syncthreads();
        for (int q = tid; q < 2560; q += 256) {
            int o = q & 63, kk = q >> 6;
            int ii = kk / 5, t = kk - ii * 5, i = i0 + ii;
            Bs[kk][o] = (t == 0) ? wb[o * 128 + i] : ws[(o * 128 + i) * 4 + (t - 1)];
        }
        for (int q = tid; q < 1024; q += 256) {
            int pos = q & 127, ii = q >> 7;
            int i = i0 + ii;
            int m = m0 + pos;
            int bb = m / 196, r = m - bb * 196;
            int y = r / 14, xx = r - y * 14;
            int c = i >> 2, j = i & 3;
            int pix = ((bb * 32 + c) * 15 + y + (j >> 1)) * 15 + xx + (j & 1);
            float f0 = g_F2a[pix];
            float4 f4 = g_F2b[pix];
            As[ii * 5 + 0][pos] = f0;
            As[ii * 5 + 1][pos] = f4.x;
            As[ii * 5 + 2][pos] = f4.y;
            As[ii * 5 + 3][pos] = f4.z;
            As[ii * 5 + 4][pos] = f4.w;
        }
        __syncthreads();
#pragma unroll 5
        for (int k = 0; k < 40; k++) {
            float4 av = *(const float4*)&As[k][px * 4];
            float4 b0 = *(const float4*)&Bs[k][oy * 8];
            float4 b1 = *(const float4*)&Bs[k][oy * 8 + 4];
            float aa[4] = {av.x, av.y, av.z, av.w};
            float bb[8] = {b0.x, b0.y, b0.z, b0.w, b1.x, b1.y, b1.z, b1.w};
#pragma unroll
            for (int a = 0; a < 4; a++)
#pragma unroll
                for (int o = 0; o < 8; o++) acc[a][o] = fmaf(aa[a], bb[o], acc[a][o]);
        }
    }
#pragma unroll
    for (int a = 0; a < 4; a++) {
        int m = m0 + px * 4 + a;
        int bb = m / 196, r = m - bb * 196;
#pragma unroll
        for (int o = 0; o < 8; o++)
            g_h2[(bb * 64 + oy * 8 + o) * 196 + r] = acc[a][o];
    }
}

// bn2 + relu + maxpool -> flat [1024,3136]
__global__ void pool2_kernel() {
    int idx = blockIdx.x * 256 + threadIdx.x;
    if (idx >= 3211264) return;
    int xo = idx % 7; int t1 = idx / 7;
    int yo = t1 % 7;  int t2 = t1 / 7;
    int c  = t2 & 63;  int b  = t2 >> 6;
    float sc = g_bn2p[2 * c], sh = g_bn2p[2 * c + 1];
    const float* p = g_h2 + (b * 64 + c) * 196 + (2 * yo) * 14 + 2 * xo;
    float m = fmaf(p[0], sc, sh);
    m = fmaxf(m, fmaf(p[1], sc, sh));
    m = fmaxf(m, fmaf(p[14], sc, sh));
    m = fmaxf(m, fmaf(p[15], sc, sh));
    g_p2[idx] = fmaxf(m, 0.f);
}

// fc1: [1024,3136]x[64,3136]^T, k-split 8, 64-row tiles
__global__ __launch_bounds__(256) void fc1_kernel(const float* __restrict__ w) {
    __shared__ float Xs[56][64];
    __shared__ float Ws[56][64];
    const int tid = threadIdx.x;
    const int b0 = blockIdx.x * 64;
    const int ks = blockIdx.y;          // 0..7, each 392 k
    const int o0 = (tid & 15) * 4, r0 = (tid >> 4) * 4;
    float acc[4][4];
#pragma unroll
    for (int a = 0; a < 4; a++)
#pragma unroll
        for (int o = 0; o < 4; o++) acc[a][o] = 0.f;
    for (int cc = 0; cc < 7; cc++) {
        int k0 = ks * 392 + cc * 56;
        __syncthreads();
        for (int q = tid; q < 3584; q += 256) {
            int k = q / 64, rr = q & 63;
            Xs[k][rr] = g_p2[(b0 + rr) * 3136 + k0 + k];
            Ws[k][rr] = w[rr * 3136 + k0 + k];
        }
        __syncthreads();
#pragma unroll 8
        for (int k = 0; k < 56; k++) {
            float4 xv = *(const float4*)&Xs[k][r0];
            float4 wv = *(const float4*)&Ws[k][o0];
            float aa[4] = {xv.x, xv.y, xv.z, xv.w};
            float bb[4] = {wv.x, wv.y, wv.z, wv.w};
#pragma unroll
            for (int a = 0; a < 4; a++)
#pragma unroll
                for (int o = 0; o < 4; o++) acc[a][o] = fmaf(aa[a], bb[o], acc[a][o]);
        }
    }
#pragma unroll
    for (int a = 0; a < 4; a++)
#pragma unroll
        for (int o = 0; o < 4; o++)
            g_fc1p[ks * 65536 + (b0 + r0 + a) * 64 + o0 + o] = acc[a][o];
}

// sum k-split partials + bias, compute bn3 stats per feature
__global__ void bn3_kernel(const float* __restrict__ fc1b,
                           const float* __restrict__ gam, const float* __restrict__ bet) {
    __shared__ float rs[256], rq[256];
    int c = blockIdx.x;
    float bias = fc1b[c];
    float s = 0.f, ss = 0.f;
    for (int b = threadIdx.x; b < 1024; b += 256) {
        float v = bias;
#pragma unroll
        for (int k = 0; k < 8; k++) v += g_fc1p[k * 65536 + b * 64 + c];
        g_a1[b * 64 + c] = v;
        s += v; ss += v * v;
    }
    rs[threadIdx.x] = s; rq[threadIdx.x] = ss; __syncthreads();
    for (int st = 128; st; st >>= 1) {
        if (threadIdx.x < st) { rs[threadIdx.x] += rs[threadIdx.x + st]; rq[threadIdx.x] += rq[threadIdx.x + st]; }
        __syncthreads();
    }
    if (threadIdx.x == 0) {
        float mean = rs[0] / 1024.f;
        float var  = rq[0] / 1024.f - mean * mean;
        float sc   = gam[c] * rsqrtf(var + EPSBN);
        g_bn3p[2 * c + 0] = sc;
        g_bn3p[2 * c + 1] = bet[c] - mean * sc;
    }
}

__global__ void final_kernel(const float* __restrict__ w2, const float* __restrict__ b2,
                             float* __restrict__ out) {
    __shared__ float hm[64];
    int b = blockIdx.x, tid = threadIdx.x;
    float v = g_a1[b * 64 + tid];
    hm[tid] = fmaxf(fmaf(v, g_bn3p[2 * tid], g_bn3p[2 * tid + 1]), 0.f);
    __syncthreads();
    if (tid < 10) {
        float acc = b2[tid];
#pragma unroll
        for (int k = 0; k < 64; k++) acc = fmaf(hm[k], w2[tid * 64 + k], acc);
        out[b * 10 + tid] = acc;
    }
}

extern "C" void kernel_launch(void* const* d_in, const int* in_sizes, int n_in,
                              void* d_out, int out_size) {
    const float* x    = (const float*)d_in[0];
    const float* bw1  = (const float*)d_in[1];
    const float* sw1  = (const float*)d_in[2];
    const float* bn1g = (const float*)d_in[3];
    const float* bn1b = (const float*)d_in[4];
    const float* bw2  = (const float*)d_in[5];
    const float* sw2  = (const float*)d_in[6];
    const float* bn2g = (const float*)d_in[7];
    const float* bn2b = (const float*)d_in[8];
    const float* fc1w = (const float*)d_in[9];
    const float* fc1b = (const float*)d_in[10];
    const float* bn3g = (const float*)d_in[11];
    const float* bn3b = (const float*)d_in[12];
    const float* fc2w = (const float*)d_in[13];
    const float* fc2b = (const float*)d_in[14];
    float* out = (float*)d_out;

    feat1_kernel<<<12288, 256>>>(x);
    conv1_gemm<<<3844, 256>>>(bw1, sw1);
    reduce1_kernel<<<dim3(64, 32), 256>>>();
    finalize_bn<<<32, 32>>>(0, bn1g, bn1b);
    pool1feat_kernel<<<28800, 256>>>();
    conv2_gemm<<<1568, 256>>>(bw2, sw2);
    reduce2_kernel<<<dim3(32, 64), 256>>>();
    finalize_bn<<<64, 32>>>(1, bn2g, bn2b);
    pool2_kernel<<<12544, 256>>>();
    fc1_kernel<<<dim3(16, 8), 256>>>(fc1w);
    bn3_kernel<<<64, 256>>>(fc1b, bn3g, bn3b);
    final_kernel<<<1024, 64>>>(fc2w, fc2b, out);
}

// round 3
// speedup vs baseline: 1.2741x; 1.2741x over previous
#include <cuda_runtime.h>

#define EPSBN 1e-5f

// ---------------- device scratch ----------------
__device__ float  g_F1a[3145728];
__device__ float4 g_F1b[3145728];
__device__ float  g_h1[31490048];          // [1024,32,961]
__device__ float  g_part1[32*64*2];
__device__ float  g_bn1p[64];
__device__ float  g_F2a[7372800];          // [1024,32,15,15]
__device__ float4 g_F2b[7372800];
__device__ float  g_h2[12845056];          // [1024,64,196]
__device__ float  g_part2[64*32*2];
__device__ float  g_bn2p[128];
__device__ float  g_p2[3211264];           // [1024,3136]
__device__ float  g_fc1p[8*65536];
__device__ float  g_a1[65536];
__device__ float  g_bn3p[128];
__device__ float  g_W1[60*32];             // prepacked conv1 weights [k][o]
__device__ float  g_W2[640*64];            // prepacked conv2 weights [k][o]

// ---------------- f32x2 packed math ----------------
__device__ __forceinline__ void fma2(unsigned long long &d, unsigned long long a, unsigned long long b) {
    asm("fma.rn.f32x2 %0, %1, %2, %3;" : "=l"(d) : "l"(a), "l"(b), "l"(d));
}
__device__ __forceinline__ unsigned long long pack2(float v) {
    unsigned long long r;
    asm("mov.b64 %0, {%1, %1};" : "=l"(r) : "r"(__float_as_uint(v)));
    return r;
}
__device__ __forceinline__ float2 u2f(unsigned long long u) {
    float2 f;
    f.x = __uint_as_float((unsigned)u);
    f.y = __uint_as_float((unsigned)(u >> 32));
    return f;
}

// silu + 4 cubic B-spline bases on knots {-7,-5,...,7}
__device__ __forceinline__ void feats5(float v, float f[5]) {
    f[0] = v / (1.f + expf(-v));
    float b[7];
#pragma unroll
    for (int j = 0; j < 7; j++) {
        float gj = 2.f * j - 7.f;
        b[j] = (v >= gj && v < gj + 2.f) ? 1.f : 0.f;
    }
#pragma unroll
    for (int p = 1; p <= 3; p++) {
        float inv = 1.f / (2.f * p);
#pragma unroll
        for (int j = 0; j < 7 - p; j++) {
            float gj = 2.f * j - 7.f;
            b[j] = ((v - gj) * b[j] + (gj + 2.f * (p + 1) - v) * b[j + 1]) * inv;
        }
    }
    f[1] = b[0]; f[2] = b[1]; f[3] = b[2]; f[4] = b[3];
}

// ---------------- weight prepack: [out][in][5] -> [k=in*5+t][out] ----------------
__global__ void wprep_kernel(const float* __restrict__ wb1, const float* __restrict__ ws1,
                             const float* __restrict__ wb2, const float* __restrict__ ws2) {
    int q = blockIdx.x * 256 + threadIdx.x;
    if (q < 1920) {
        int o = q & 31, kk = q >> 5;
        int ii = kk / 5, t = kk - ii * 5;
        g_W1[kk * 32 + o] = (t == 0) ? wb1[o * 12 + ii] : ws1[(o * 12 + ii) * 4 + (t - 1)];
    }
    int q2 = q - 1920;
    if (q2 >= 0 && q2 < 40960) {
        int o = q2 & 63, kk = q2 >> 6;
        int ii = kk / 5, t = kk - ii * 5;
        g_W2[kk * 64 + o] = (t == 0) ? wb2[o * 128 + ii] : ws2[(o * 128 + ii) * 4 + (t - 1)];
    }
}

__global__ void feat1_kernel(const float* __restrict__ x) {
    int i = blockIdx.x * 256 + threadIdx.x;
    if (i >= 3145728) return;
    float f[5]; feats5(x[i], f);
    g_F1a[i] = f[0];
    g_F1b[i] = make_float4(f[1], f[2], f[3], f[4]);
}

// conv1 GEMM: M=984064, N=32, K=60 (2 chunks of 30), f32x2 inner loop
__global__ __launch_bounds__(256) void conv1_gemm() {
    __shared__ __align__(16) float As[30][256];
    __shared__ __align__(16) float Bs[30][32];
    __shared__ int ipb[256];
    const int tid = threadIdx.x;
    const int m0 = blockIdx.x * 256;
    const int px = tid & 63, oy = tid >> 6;
    {
        int m = m0 + tid;
        int bb = m / 961, r = m - bb * 961;
        int y = r / 31, xx = r - y * 31;
        ipb[tid] = ((bb * 3) * 32 + y) * 32 + xx;
    }
    unsigned long long acc2[4][4];
#pragma unroll
    for (int a = 0; a < 4; a++)
#pragma unroll
        for (int p = 0; p < 4; p++) acc2[a][p] = 0ull;

    for (int chunk = 0; chunk < 2; chunk++) {
        __syncthreads();
        for (int q = tid; q < 960; q += 256) {
            int o = q & 31, kk = q >> 5;
            Bs[kk][o] = g_W1[(chunk * 30 + kk) * 32 + o];
        }
        for (int q = tid; q < 1536; q += 256) {
            int pos = q & 255, ii = q >> 8;
            int i = chunk * 6 + ii;
            int c = i >> 2, j = i & 3;
            int pix = ipb[pos] + c * 1024 + ((j & 2) << 4) + (j & 1);
            float f0 = g_F1a[pix];
            float4 f4 = g_F1b[pix];
            As[ii * 5 + 0][pos] = f0;
            As[ii * 5 + 1][pos] = f4.x;
            As[ii * 5 + 2][pos] = f4.y;
            As[ii * 5 + 3][pos] = f4.z;
            As[ii * 5 + 4][pos] = f4.w;
        }
        __syncthreads();
#pragma unroll 5
        for (int k = 0; k < 30; k++) {
            float4 av = *(const float4*)&As[k][px * 4];
            ulonglong2 b01 = *(const ulonglong2*)&Bs[k][oy * 8];
            ulonglong2 b23 = *(const ulonglong2*)&Bs[k][oy * 8 + 4];
            float aa[4] = {av.x, av.y, av.z, av.w};
#pragma unroll
            for (int a = 0; a < 4; a++) {
                unsigned long long a2 = pack2(aa[a]);
                fma2(acc2[a][0], a2, b01.x);
                fma2(acc2[a][1], a2, b01.y);
                fma2(acc2[a][2], a2, b23.x);
                fma2(acc2[a][3], a2, b23.y);
            }
        }
    }
#pragma unroll
    for (int a = 0; a < 4; a++) {
        int m = m0 + px * 4 + a;
        int bb = m / 961, r = m - bb * 961;
#pragma unroll
        for (int p = 0; p < 4; p++) {
            float2 v = u2f(acc2[a][p]);
            g_h1[(bb * 32 + oy * 8 + 2 * p + 0) * 961 + r] = v.x;
            g_h1[(bb * 32 + oy * 8 + 2 * p + 1) * 961 + r] = v.y;
        }
    }
}

__global__ void reduce1_kernel() {
    __shared__ float rs[256], rq[256];
    int c = blockIdx.y, b0 = blockIdx.x * 16;
    float s = 0.f, ss = 0.f;
    for (int b = b0; b < b0 + 16; b++) {
        const float* p = g_h1 + (b * 32 + c) * 961;
        for (int i = threadIdx.x; i < 961; i += 256) { float v = p[i]; s += v; ss += v * v; }
    }
    rs[threadIdx.x] = s; rq[threadIdx.x] = ss; __syncthreads();
    for (int st = 128; st; st >>= 1) {
        if (threadIdx.x < st) { rs[threadIdx.x] += rs[threadIdx.x + st]; rq[threadIdx.x] += rq[threadIdx.x + st]; }
        __syncthreads();
    }
    if (threadIdx.x == 0) {
        g_part1[(c * 64 + blockIdx.x) * 2 + 0] = rs[0];
        g_part1[(c * 64 + blockIdx.x) * 2 + 1] = rq[0];
    }
}

__global__ void reduce2_kernel() {
    __shared__ float rs[256], rq[256];
    int c = blockIdx.y, b0 = blockIdx.x * 32;
    float s = 0.f, ss = 0.f;
    for (int b = b0; b < b0 + 32; b++) {
        const float* p = g_h2 + (b * 64 + c) * 196;
        for (int i = threadIdx.x; i < 196; i += 256) { float v = p[i]; s += v; ss += v * v; }
    }
    rs[threadIdx.x] = s; rq[threadIdx.x] = ss; __syncthreads();
    for (int st = 128; st; st >>= 1) {
        if (threadIdx.x < st) { rs[threadIdx.x] += rs[threadIdx.x + st]; rq[threadIdx.x] += rq[threadIdx.x + st]; }
        __syncthreads();
    }
    if (threadIdx.x == 0) {
        g_part2[(c * 32 + blockIdx.x) * 2 + 0] = rs[0];
        g_part2[(c * 32 + blockIdx.x) * 2 + 1] = rq[0];
    }
}

__global__ void finalize_bn(int which, const float* __restrict__ gam, const float* __restrict__ bet) {
    int c = blockIdx.x;
    const float* part; float* out2; int nparts; float invc;
    if (which == 0) { part = g_part1; out2 = g_bn1p; nparts = 64; invc = 1.f / 984064.f; }
    else            { part = g_part2; out2 = g_bn2p; nparts = 32; invc = 1.f / 200704.f; }
    float s = 0.f, ss = 0.f;
    for (int i = threadIdx.x; i < nparts; i += 32) {
        s  += part[(c * nparts + i) * 2 + 0];
        ss += part[(c * nparts + i) * 2 + 1];
    }
#pragma unroll
    for (int off = 16; off; off >>= 1) {
        s  += __shfl_down_sync(0xffffffffu, s, off);
        ss += __shfl_down_sync(0xffffffffu, ss, off);
    }
    if (threadIdx.x == 0) {
        float mean = s * invc;
        float var  = ss * invc - mean * mean;
        float sc   = gam[c] * rsqrtf(var + EPSBN);
        out2[2 * c + 0] = sc;
        out2[2 * c + 1] = bet[c] - mean * sc;
    }
}

// bn1 + relu + maxpool + conv2 feature generation
__global__ void pool1feat_kernel() {
    int idx = blockIdx.x * 256 + threadIdx.x;
    if (idx >= 7372800) return;
    int xo = idx % 15; int t1 = idx / 15;
    int yo = t1 % 15;  int t2 = t1 / 15;
    int c  = t2 & 31;  int b  = t2 >> 5;
    float sc = g_bn1p[2 * c], sh = g_bn1p[2 * c + 1];
    const float* p = g_h1 + (b * 32 + c) * 961 + (2 * yo) * 31 + 2 * xo;
    float m = fmaf(p[0], sc, sh);
    m = fmaxf(m, fmaf(p[1], sc, sh));
    m = fmaxf(m, fmaf(p[31], sc, sh));
    m = fmaxf(m, fmaf(p[32], sc, sh));
    float v = fmaxf(m, 0.f);
    float f[5]; feats5(v, f);
    g_F2a[idx] = f[0];
    g_F2b[idx] = make_float4(f[1], f[2], f[3], f[4]);
}

// conv2 GEMM: M=200704, N=64, K=640 (16 chunks of 40), f32x2 inner loop
__global__ __launch_bounds__(256) void conv2_gemm() {
    __shared__ __align__(16) float As[40][128];
    __shared__ __align__(16) float Bs[40][64];
    __shared__ int ipb[128];
    const int tid = threadIdx.x;
    const int m0 = blockIdx.x * 128;
    const int px = tid & 31, oy = tid >> 5;
    if (tid < 128) {
        int m = m0 + tid;
        int bb = m / 196, r = m - bb * 196;
        int y = r / 14, xx = r - y * 14;
        ipb[tid] = ((bb * 32) * 15 + y) * 15 + xx;
    }
    unsigned long long acc2[4][4];
#pragma unroll
    for (int a = 0; a < 4; a++)
#pragma unroll
        for (int p = 0; p < 4; p++) acc2[a][p] = 0ull;

    for (int chunk = 0; chunk < 16; chunk++) {
        __syncthreads();
        for (int q = tid; q < 2560; q += 256) {
            int o = q & 63, kk = q >> 6;
            Bs[kk][o] = g_W2[(chunk * 40 + kk) * 64 + o];
        }
        for (int q = tid; q < 1024; q += 256) {
            int pos = q & 127, ii = q >> 7;
            int i = chunk * 8 + ii;
            int c = i >> 2, j = i & 3;
            int pix = ipb[pos] + c * 225 + (j >> 1) * 15 + (j & 1);
            float f0 = g_F2a[pix];
            float4 f4 = g_F2b[pix];
            As[ii * 5 + 0][pos] = f0;
            As[ii * 5 + 1][pos] = f4.x;
            As[ii * 5 + 2][pos] = f4.y;
            As[ii * 5 + 3][pos] = f4.z;
            As[ii * 5 + 4][pos] = f4.w;
        }
        __syncthreads();
#pragma unroll 5
        for (int k = 0; k < 40; k++) {
            float4 av = *(const float4*)&As[k][px * 4];
            ulonglong2 b01 = *(const ulonglong2*)&Bs[k][oy * 8];
            ulonglong2 b23 = *(const ulonglong2*)&Bs[k][oy * 8 + 4];
            float aa[4] = {av.x, av.y, av.z, av.w};
#pragma unroll
            for (int a = 0; a < 4; a++) {
                unsigned long long a2 = pack2(aa[a]);
                fma2(acc2[a][0], a2, b01.x);
                fma2(acc2[a][1], a2, b01.y);
                fma2(acc2[a][2], a2, b23.x);
                fma2(acc2[a][3], a2, b23.y);
            }
        }
    }
#pragma unroll
    for (int a = 0; a < 4; a++) {
        int m = m0 + px * 4 + a;
        int bb = m / 196, r = m - bb * 196;
#pragma unroll
        for (int p = 0; p < 4; p++) {
            float2 v = u2f(acc2[a][p]);
            g_h2[(bb * 64 + oy * 8 + 2 * p + 0) * 196 + r] = v.x;
            g_h2[(bb * 64 + oy * 8 + 2 * p + 1) * 196 + r] = v.y;
        }
    }
}

// bn2 + relu + maxpool -> flat [1024,3136]
__global__ void pool2_kernel() {
    int idx = blockIdx.x * 256 + threadIdx.x;
    if (idx >= 3211264) return;
    int xo = idx % 7; int t1 = idx / 7;
    int yo = t1 % 7;  int t2 = t1 / 7;
    int c  = t2 & 63;  int b  = t2 >> 6;
    float sc = g_bn2p[2 * c], sh = g_bn2p[2 * c + 1];
    const float* p = g_h2 + (b * 64 + c) * 196 + (2 * yo) * 14 + 2 * xo;
    float m = fmaf(p[0], sc, sh);
    m = fmaxf(m, fmaf(p[1], sc, sh));
    m = fmaxf(m, fmaf(p[14], sc, sh));
    m = fmaxf(m, fmaf(p[15], sc, sh));
    g_p2[idx] = fmaxf(m, 0.f);
}

// fc1: [1024,3136]x[64,3136]^T, k-split 8, 64-row tiles, f32x2
__global__ __launch_bounds__(256) void fc1_kernel(const float* __restrict__ w) {
    __shared__ __align__(16) float Xs[56][64];
    __shared__ __align__(16) float Ws[56][64];
    const int tid = threadIdx.x;
    const int b0 = blockIdx.x * 64;
    const int ks = blockIdx.y;
    const int o0 = (tid & 15) * 4, r0 = (tid >> 4) * 4;
    unsigned long long acc2[4][2];
#pragma unroll
    for (int a = 0; a < 4; a++) { acc2[a][0] = 0ull; acc2[a][1] = 0ull; }
    for (int cc = 0; cc < 7; cc++) {
        int k0 = ks * 392 + cc * 56;
        __syncthreads();
        for (int q = tid; q < 3584; q += 256) {
            int k = q / 64, rr = q & 63;
            Xs[k][rr] = g_p2[(b0 + rr) * 3136 + k0 + k];
            Ws[k][rr] = w[rr * 3136 + k0 + k];
        }
        __syncthreads();
#pragma unroll 8
        for (int k = 0; k < 56; k++) {
            float4 xv = *(const float4*)&Xs[k][r0];
            ulonglong2 wv = *(const ulonglong2*)&Ws[k][o0];
            float aa[4] = {xv.x, xv.y, xv.z, xv.w};
#pragma unroll
            for (int a = 0; a < 4; a++) {
                unsigned long long a2 = pack2(aa[a]);
                fma2(acc2[a][0], a2, wv.x);
                fma2(acc2[a][1], a2, wv.y);
            }
        }
    }
#pragma unroll
    for (int a = 0; a < 4; a++) {
        float2 v0 = u2f(acc2[a][0]);
        float2 v1 = u2f(acc2[a][1]);
        float* dst = g_fc1p + ks * 65536 + (b0 + r0 + a) * 64 + o0;
        dst[0] = v0.x; dst[1] = v0.y; dst[2] = v1.x; dst[3] = v1.y;
    }
}

__global__ void bn3_kernel(const float* __restrict__ fc1b,
                           const float* __restrict__ gam, const float* __restrict__ bet) {
    __shared__ float rs[256], rq[256];
    int c = blockIdx.x;
    float bias = fc1b[c];
    float s = 0.f, ss = 0.f;
    for (int b = threadIdx.x; b < 1024; b += 256) {
        float v = bias;
#pragma unroll
        for (int k = 0; k < 8; k++) v += g_fc1p[k * 65536 + b * 64 + c];
        g_a1[b * 64 + c] = v;
        s += v; ss += v * v;
    }
    rs[threadIdx.x] = s; rq[threadIdx.x] = ss; __syncthreads();
    for (int st = 128; st; st >>= 1) {
        if (threadIdx.x < st) { rs[threadIdx.x] += rs[threadIdx.x + st]; rq[threadIdx.x] += rq[threadIdx.x + st]; }
        __syncthreads();
    }
    if (threadIdx.x == 0) {
        float mean = rs[0] / 1024.f;
        float var  = rq[0] / 1024.f - mean * mean;
        float sc   = gam[c] * rsqrtf(var + EPSBN);
        g_bn3p[2 * c + 0] = sc;
        g_bn3p[2 * c + 1] = bet[c] - mean * sc;
    }
}

__global__ void final_kernel(const float* __restrict__ w2, const float* __restrict__ b2,
                             float* __restrict__ out) {
    __shared__ float hm[64];
    int b = blockIdx.x, tid = threadIdx.x;
    float v = g_a1[b * 64 + tid];
    hm[tid] = fmaxf(fmaf(v, g_bn3p[2 * tid], g_bn3p[2 * tid + 1]), 0.f);
    __syncthreads();
    if (tid < 10) {
        float acc = b2[tid];
#pragma unroll
        for (int k = 0; k < 64; k++) acc = fmaf(hm[k], w2[tid * 64 + k], acc);
        out[b * 10 + tid] = acc;
    }
}

extern "C" void kernel_launch(void* const* d_in, const int* in_sizes, int n_in,
                              void* d_out, int out_size) {
    const float* x    = (const float*)d_in[0];
    const float* bw1  = (const float*)d_in[1];
    const float* sw1  = (const float*)d_in[2];
    const float* bn1g = (const float*)d_in[3];
    const float* bn1b = (const float*)d_in[4];
    const float* bw2  = (const float*)d_in[5];
    const float* sw2  = (const float*)d_in[6];
    const float* bn2g = (const float*)d_in[7];
    const float* bn2b = (const float*)d_in[8];
    const float* fc1w = (const float*)d_in[9];
    const float* fc1b = (const float*)d_in[10];
    const float* bn3g = (const float*)d_in[11];
    const float* bn3b = (const float*)d_in[12];
    const float* fc2w = (const float*)d_in[13];
    const float* fc2b = (const float*)d_in[14];
    float* out = (float*)d_out;

    wprep_kernel<<<168, 256>>>(bw1, sw1, bw2, sw2);
    feat1_kernel<<<12288, 256>>>(x);
    conv1_gemm<<<3844, 256>>>();
    reduce1_kernel<<<dim3(64, 32), 256>>>();
    finalize_bn<<<32, 32>>>(0, bn1g, bn1b);
    pool1feat_kernel<<<28800, 256>>>();
    conv2_gemm<<<1568, 256>>>();
    reduce2_kernel<<<dim3(32, 64), 256>>>();
    finalize_bn<<<64, 32>>>(1, bn2g, bn2b);
    pool2_kernel<<<12544, 256>>>();
    fc1_kernel<<<dim3(16, 8), 256>>>(fc1w);
    bn3_kernel<<<64, 256>>>(fc1b, bn3g, bn3b);
    final_kernel<<<1024, 64>>>(fc2w, fc2b, out);
}